// round 4
// baseline (speedup 1.0000x reference)
#include <cuda_runtime.h>
#include <math.h>

// ---------------------------------------------------------------------------
// GNNLoss fused single-kernel (R4).
//
// R4: 4-bit filter table (2 nodes/byte, 100KB) so TWO 1024-thread CTAs fit
// per SM -> 100% occupancy (R3 was capped at 50% by the 200KB 8-bit table).
// Filter false positives (1/15 of differing-key pairs) fall through to an
// exact u16 key compare via predicated LDG. Exact result.
//
// key[node] = (pi==0) ? 0 : (batch<<10)|pi   (u16; batch<16, pi<1000)
// nib[node] = (key==0) ? 0 : 1 + (key % 15)  (4-bit, packed 2/byte, smem)
//
// Persistent grid + software grid barriers (grid sized by occupancy API so
// all CTAs are co-resident): phase1 nodes -> barrier -> phase2 edges ->
// barrier -> block0 reduces partials, writes 5 outputs, resets barriers.
//
// Focal math: a=|x|, em=e^-a, w=1+em, L=log(w), q=em*rcp.approx(w);
// match=(x>=0)==t: ce = match? L : a+L ; 1-p_t = match? q : 1-q
// loss = (t?0.25:0.75) * ce * (1-p_t)^2   (3 MUFU + ~10 FFMA/ALU per elem)
// ---------------------------------------------------------------------------

#define MAX_NODES  262144
#define MAX_BLOCKS 512

__device__ __align__(16) unsigned short g_keys[MAX_NODES];
__device__ __align__(16) unsigned char  g_nib[MAX_NODES / 2];
__device__ float g_part_es[MAX_BLOCKS];
__device__ int   g_part_ec[MAX_BLOCKS];
__device__ float g_part_ns[MAX_BLOCKS];
__device__ int   g_part_nc[MAX_BLOCKS];
__device__ unsigned int g_bar0;   // zero-init; reset by block 0 each run
__device__ unsigned int g_bar1;

__device__ __forceinline__ float rcp_approx(float x) {
    float y;
    asm("rcp.approx.f32 %0, %1;" : "=f"(y) : "f"(x));
    return y;
}

__device__ __forceinline__ float focal_term(float x, bool t) {
    float a  = fabsf(x);
    float em = __expf(-a);             // MUFU.EX2 (+mul)
    float w  = 1.0f + em;              // w in [1,2]
    float L  = __logf(w);              // MUFU.LG2 (+mul)
    float q  = em * rcp_approx(w);     // 1 - sigmoid(|x|), MUFU.RCP ~1ulp
    bool  m  = ((x >= 0.0f) == t);
    float omp = m ? q : (1.0f - q);    // 1 - p_t
    float ce  = m ? L : (a + L);       // BCE-with-logits
    float at  = t ? 0.25f : 0.75f;     // ALPHA=0.25
    return at * ce * omp * omp;        // GAMMA=2
}

__device__ __forceinline__ unsigned short make_key(int p, int b) {
    return (p == 0) ? (unsigned short)0 : (unsigned short)((b << 10) | p);
}

__device__ __forceinline__ unsigned int make_nib(unsigned short key) {
    return (key == 0) ? 0u : (1u + (unsigned int)(key % 15));
}

// block reduction of (float, int) -> one slot per block
__device__ __forceinline__ void block_reduce_store(float s, int c,
                                                   float* ps, int* pc) {
    #pragma unroll
    for (int o = 16; o > 0; o >>= 1) {
        s += __shfl_down_sync(0xFFFFFFFFu, s, o);
        c += __shfl_down_sync(0xFFFFFFFFu, c, o);
    }
    __shared__ float sh_s[32];
    __shared__ int   sh_c[32];
    int lane = threadIdx.x & 31;
    int wid  = threadIdx.x >> 5;
    if (lane == 0) { sh_s[wid] = s; sh_c[wid] = c; }
    __syncthreads();
    int nw = (blockDim.x + 31) >> 5;
    if (wid == 0) {
        s = (lane < nw) ? sh_s[lane] : 0.0f;
        c = (lane < nw) ? sh_c[lane] : 0;
        #pragma unroll
        for (int o = 16; o > 0; o >>= 1) {
            s += __shfl_down_sync(0xFFFFFFFFu, s, o);
            c += __shfl_down_sync(0xFFFFFFFFu, c, o);
        }
        if (lane == 0) { ps[blockIdx.x] = s; pc[blockIdx.x] = c; }
    }
    __syncthreads();
}

__device__ __forceinline__ void grid_barrier(unsigned int* bar, int nb) {
    __syncthreads();
    if (threadIdx.x == 0) {
        __threadfence();
        atomicAdd(bar, 1u);
        while (*(volatile unsigned int*)bar < (unsigned int)nb) { }
    }
    __syncthreads();
    __threadfence();
}

__device__ __forceinline__ bool edge_target(const unsigned char* sh,
                                            int sidx, int didx) {
    unsigned int hs = (sh[sidx >> 1] >> ((sidx & 1) << 2)) & 0xFu;
    unsigned int hd = (sh[didx >> 1] >> ((didx & 1) << 2)) & 0xFu;
    bool t = false;
    if ((hs == hd) & (hs != 0u)) {              // ~7% of edges
        t = (__ldg(&g_keys[sidx]) == __ldg(&g_keys[didx]));
    }
    return t;
}

__global__ void __launch_bounds__(1024, 2)
fused_kernel(const float* __restrict__ edge_logits,
             const float* __restrict__ node_logits,
             const int*   __restrict__ batch,
             const int*   __restrict__ pinst,
             const int*   __restrict__ src,
             const int*   __restrict__ dst,
             int E, int N, int nvec,
             float* __restrict__ out) {
    extern __shared__ unsigned char sh[];
    int tid     = threadIdx.x;
    int nb      = gridDim.x;
    int gtid    = blockIdx.x * blockDim.x + tid;
    int gstride = nb * blockDim.x;

    // ---- phase 1: nodes, processed in pairs (one packed nibble byte) ----
    float ns = 0.0f; int nc = 0;
    {
        int npairs = N >> 1;  // N=200K even; odd tail handled below
        const int2*   p2 = (const int2*)pinst;
        const int2*   b2 = (const int2*)batch;
        const float2* x2 = (const float2*)node_logits;
        for (int j = gtid; j < npairs; j += gstride) {
            int2   p = p2[j];
            int2   b = b2[j];
            float2 x = x2[j];
            unsigned short k0 = make_key(p.x, b.x);
            unsigned short k1 = make_key(p.y, b.y);
            g_keys[2 * j]     = k0;
            g_keys[2 * j + 1] = k1;
            g_nib[j] = (unsigned char)(make_nib(k0) | (make_nib(k1) << 4));
            bool t0 = (p.x != 0), t1 = (p.y != 0);
            ns += focal_term(x.x, t0) + focal_term(x.y, t1);
            nc += (((x.x > 0.0f) == t0) ? 1 : 0)
                + (((x.y > 0.0f) == t1) ? 1 : 0);
        }
        if ((N & 1) && gtid == 0) {   // odd-N tail
            int i = N - 1;
            unsigned short k = make_key(pinst[i], batch[i]);
            g_keys[i] = k;
            g_nib[i >> 1] = (unsigned char)make_nib(k);
            bool t = (pinst[i] != 0);
            float x = node_logits[i];
            ns += focal_term(x, t);
            nc += ((x > 0.0f) == t) ? 1 : 0;
        }
    }
    block_reduce_store(ns, nc, g_part_ns, g_part_nc);

    grid_barrier(&g_bar0, nb);   // key/nib tables complete, visible in L2

    // ---- broadcast nibble table into shared memory ----
    int nbytes = (N + 1) >> 1;
    int nw4 = (nbytes + 15) >> 4;
    const uint4* hv = (const uint4*)g_nib;
    uint4* s4 = (uint4*)sh;
    for (int i = tid; i < nw4; i += blockDim.x) s4[i] = hv[i];
    __syncthreads();

    // ---- phase 2: edges (vec4 streams + smem nibble filter) ----
    const float4* elv = (const float4*)edge_logits;
    const int4*   svp = (const int4*)src;
    const int4*   dvp = (const int4*)dst;
    float es = 0.0f; int ec = 0;
    for (int i = gtid; i < nvec; i += gstride) {
        float4 x  = __ldcs(&elv[i]);   // streaming: keep L1 for key lookups
        int4   sv = __ldcs(&svp[i]);
        int4   dv = __ldcs(&dvp[i]);

        bool t0 = edge_target(sh, sv.x, dv.x);
        bool t1 = edge_target(sh, sv.y, dv.y);
        bool t2 = edge_target(sh, sv.z, dv.z);
        bool t3 = edge_target(sh, sv.w, dv.w);

        es += focal_term(x.x, t0);
        es += focal_term(x.y, t1);
        es += focal_term(x.z, t2);
        es += focal_term(x.w, t3);

        ec += ((x.x > 0.0f) == t0) ? 1 : 0;
        ec += ((x.y > 0.0f) == t1) ? 1 : 0;
        ec += ((x.z > 0.0f) == t2) ? 1 : 0;
        ec += ((x.w > 0.0f) == t3) ? 1 : 0;
    }
    // tail edges (E % 4, or whole range if vec path disabled)
    if (blockIdx.x == 0 && tid == 0) {
        for (int e = nvec << 2; e < E; e++) {
            int sidx = src[e], didx = dst[e];
            unsigned short ks = g_keys[sidx], kd = g_keys[didx];
            bool t = (ks == kd) && (ks != 0);
            float x = edge_logits[e];
            es += focal_term(x, t);
            ec += ((x > 0.0f) == t) ? 1 : 0;
        }
    }
    block_reduce_store(es, ec, g_part_es, g_part_ec);

    // ---- final barrier; block 0 reduces partials and writes outputs ----
    if (tid == 0) { __threadfence(); atomicAdd(&g_bar1, 1u); }
    if (blockIdx.x != 0) return;
    if (tid == 0) {
        while (*(volatile unsigned int*)&g_bar1 < (unsigned int)nb) { }
    }
    __syncthreads();
    __threadfence();

    if (tid < 32) {
        double des = 0.0, dns = 0.0;
        int iec = 0, inc = 0;
        for (int i = tid; i < nb; i += 32) {
            des += (double)g_part_es[i];
            dns += (double)g_part_ns[i];
            iec += g_part_ec[i];
            inc += g_part_nc[i];
        }
        #pragma unroll
        for (int o = 16; o > 0; o >>= 1) {
            des += __shfl_down_sync(0xFFFFFFFFu, des, o);
            dns += __shfl_down_sync(0xFFFFFFFFu, dns, o);
            iec += __shfl_down_sync(0xFFFFFFFFu, iec, o);
            inc += __shfl_down_sync(0xFFFFFFFFu, inc, o);
        }
        if (tid == 0) {
            float edge_loss = (float)(des / (double)E);
            float node_loss = (float)(dns / (double)N);
            out[0] = edge_loss + node_loss;  // EDGE_W = NODE_W = 1
            out[1] = edge_loss;
            out[2] = node_loss;
            out[3] = (float)((double)iec / (double)E);
            out[4] = (float)((double)inc / (double)N);
            g_bar0 = 0;                      // reset for next graph replay
            g_bar1 = 0;
        }
    }
}

extern "C" void kernel_launch(void* const* d_in, const int* in_sizes, int n_in,
                              void* d_out, int out_size) {
    const float* edge_logits = (const float*)d_in[0];
    const float* node_logits = (const float*)d_in[1];
    const int*   batch       = (const int*)d_in[2];
    const int*   pinst       = (const int*)d_in[3];
    const int*   edge_index  = (const int*)d_in[4];

    int E = in_sizes[0];
    int N = in_sizes[1];
    const int* src = edge_index;
    const int* dst = edge_index + E;
    float* out = (float*)d_out;

    int nvec = ((E & 3) == 0) ? (E >> 2) : 0;

    int smem_bytes = ((((N + 1) >> 1) + 15) >> 4) << 4;  // nibble table
    cudaFuncSetAttribute(fused_kernel,
                         cudaFuncAttributeMaxDynamicSharedMemorySize,
                         smem_bytes);

    int sm_count = 148;
    cudaDeviceGetAttribute(&sm_count, cudaDevAttrMultiProcessorCount, 0);

    // size the grid by ACTUAL occupancy so the grid barrier cannot deadlock
    int per_sm = 1;
    cudaOccupancyMaxActiveBlocksPerMultiprocessor(&per_sm, fused_kernel,
                                                  1024, smem_bytes);
    if (per_sm < 1) per_sm = 1;
    int nblocks = sm_count * per_sm;
    if (nblocks > MAX_BLOCKS) nblocks = MAX_BLOCKS;

    fused_kernel<<<nblocks, 1024, smem_bytes>>>(edge_logits, node_logits,
                                                batch, pinst, src, dst,
                                                E, N, nvec, out);
}

// round 5
// speedup vs baseline: 1.7440x; 1.7440x over previous
#include <cuda_runtime.h>
#include <math.h>

// ---------------------------------------------------------------------------
// GNNLoss fused single-kernel (R5) = R3 structure + software pipelining.
//
// key[node]  = (pi==0) ? 0 : (batch<<10)|pi     (u16 exact; batch<16, pi<1000)
// hash[node] = (key==0) ? 0 : (key % 255) + 1   (u8 filter, 200KB, in smem)
// target     = hash mismatch -> false; both zero -> false;
//              else exact u16 key compare (~0.4% of edges, predicated LDG).
//
// 1 CTA/SM (smem-bound), 1024 threads. The edge loop prefetches the NEXT
// grid-stride iteration's 3 vec4 loads before processing the current one:
// doubles bytes-in-flight per SM (Little's law said R3's 32 warps x 1
// iteration ~= 12KB was exactly the 44%-of-HBM ceiling).
//
// Focal math: a=|x|, em=e^-a, w=1+em, L=log(w), q=em*rcp.approx(w);
// match=(x>=0)==t: ce = match? L : a+L ; 1-p_t = match? q : 1-q
// loss = (t?0.25:0.75) * ce * (1-p_t)^2
// ---------------------------------------------------------------------------

#define MAX_NODES  262144
#define MAX_BLOCKS 512

__device__ __align__(16) unsigned short g_keys[MAX_NODES];
__device__ __align__(16) unsigned char  g_hash[MAX_NODES];
__device__ float g_part_es[MAX_BLOCKS];
__device__ int   g_part_ec[MAX_BLOCKS];
__device__ float g_part_ns[MAX_BLOCKS];
__device__ int   g_part_nc[MAX_BLOCKS];
__device__ unsigned int g_bar0;   // zero-init; reset by block 0 each run
__device__ unsigned int g_bar1;

__device__ __forceinline__ float rcp_approx(float x) {
    float y;
    asm("rcp.approx.f32 %0, %1;" : "=f"(y) : "f"(x));
    return y;
}

__device__ __forceinline__ float focal_term(float x, bool t) {
    float a  = fabsf(x);
    float em = __expf(-a);             // MUFU.EX2 (+mul)
    float w  = 1.0f + em;              // w in [1,2]
    float L  = __logf(w);              // MUFU.LG2 (+mul)
    float q  = em * rcp_approx(w);     // 1 - sigmoid(|x|), MUFU.RCP ~1ulp
    bool  m  = ((x >= 0.0f) == t);
    float omp = m ? q : (1.0f - q);    // 1 - p_t
    float ce  = m ? L : (a + L);       // BCE-with-logits
    float at  = t ? 0.25f : 0.75f;     // ALPHA=0.25
    return at * ce * omp * omp;        // GAMMA=2
}

// block reduction of (float, int) -> one slot per block
__device__ __forceinline__ void block_reduce_store(float s, int c,
                                                   float* ps, int* pc) {
    #pragma unroll
    for (int o = 16; o > 0; o >>= 1) {
        s += __shfl_down_sync(0xFFFFFFFFu, s, o);
        c += __shfl_down_sync(0xFFFFFFFFu, c, o);
    }
    __shared__ float sh_s[32];
    __shared__ int   sh_c[32];
    int lane = threadIdx.x & 31;
    int wid  = threadIdx.x >> 5;
    if (lane == 0) { sh_s[wid] = s; sh_c[wid] = c; }
    __syncthreads();
    int nw = (blockDim.x + 31) >> 5;
    if (wid == 0) {
        s = (lane < nw) ? sh_s[lane] : 0.0f;
        c = (lane < nw) ? sh_c[lane] : 0;
        #pragma unroll
        for (int o = 16; o > 0; o >>= 1) {
            s += __shfl_down_sync(0xFFFFFFFFu, s, o);
            c += __shfl_down_sync(0xFFFFFFFFu, c, o);
        }
        if (lane == 0) { ps[blockIdx.x] = s; pc[blockIdx.x] = c; }
    }
    __syncthreads();
}

__device__ __forceinline__ void grid_barrier(unsigned int* bar, int nb) {
    __syncthreads();
    if (threadIdx.x == 0) {
        __threadfence();
        atomicAdd(bar, 1u);
        while (*(volatile unsigned int*)bar < (unsigned int)nb) { }
    }
    __syncthreads();
    __threadfence();
}

__device__ __forceinline__ bool edge_target(const unsigned char* sh,
                                            int sidx, int didx) {
    unsigned int hs = sh[sidx];
    unsigned int hd = sh[didx];
    bool t = false;
    if ((hs == hd) & (hs != 0u)) {            // ~0.4% of edges
        t = (__ldg(&g_keys[sidx]) == __ldg(&g_keys[didx]));
    }
    return t;
}

__global__ void __launch_bounds__(1024, 1)
fused_kernel(const float* __restrict__ edge_logits,
             const float* __restrict__ node_logits,
             const int*   __restrict__ batch,
             const int*   __restrict__ pinst,
             const int*   __restrict__ src,
             const int*   __restrict__ dst,
             int E, int N, int nvec,
             float* __restrict__ out) {
    extern __shared__ unsigned char sh[];
    int tid     = threadIdx.x;
    int nb      = gridDim.x;
    int gtid    = blockIdx.x * blockDim.x + tid;
    int gstride = nb * blockDim.x;

    // ---- phase 1: nodes (build key + hash tables, node loss/acc) ----
    float ns = 0.0f; int nc = 0;
    for (int i = gtid; i < N; i += gstride) {
        int p = pinst[i];
        int b = batch[i];
        unsigned short key = (p == 0) ? (unsigned short)0
                                      : (unsigned short)((b << 10) | p);
        g_keys[i] = key;
        g_hash[i] = (key == 0) ? (unsigned char)0
                               : (unsigned char)((key % 255) + 1);
        float x = node_logits[i];
        bool  t = (p != 0);
        ns += focal_term(x, t);
        nc += ((x > 0.0f) == t) ? 1 : 0;
    }
    block_reduce_store(ns, nc, g_part_ns, g_part_nc);

    grid_barrier(&g_bar0, nb);   // tables complete, visible in L2

    // ---- broadcast hash table into shared memory ----
    int nw4 = (N + 15) >> 4;
    const uint4* hv = (const uint4*)g_hash;
    uint4* s4 = (uint4*)sh;
    for (int i = tid; i < nw4; i += blockDim.x) s4[i] = hv[i];
    __syncthreads();

    // ---- phase 2: edges, software-pipelined (prefetch next iteration) ----
    const float4* elv = (const float4*)edge_logits;
    const int4*   svp = (const int4*)src;
    const int4*   dvp = (const int4*)dst;
    float es = 0.0f; int ec = 0;

    int i = gtid;
    float4 x;  int4 sv, dv;
    bool valid = (i < nvec);
    if (valid) {
        x  = __ldcs(&elv[i]);
        sv = __ldcs(&svp[i]);
        dv = __ldcs(&dvp[i]);
    }
    while (valid) {
        int j = i + gstride;
        bool vnext = (j < nvec);
        float4 xn; int4 svn, dvn;
        if (vnext) {                      // prefetch next chunk first
            xn  = __ldcs(&elv[j]);
            svn = __ldcs(&svp[j]);
            dvn = __ldcs(&dvp[j]);
        }

        bool t0 = edge_target(sh, sv.x, dv.x);
        bool t1 = edge_target(sh, sv.y, dv.y);
        bool t2 = edge_target(sh, sv.z, dv.z);
        bool t3 = edge_target(sh, sv.w, dv.w);

        es += focal_term(x.x, t0);
        es += focal_term(x.y, t1);
        es += focal_term(x.z, t2);
        es += focal_term(x.w, t3);

        ec += ((x.x > 0.0f) == t0) ? 1 : 0;
        ec += ((x.y > 0.0f) == t1) ? 1 : 0;
        ec += ((x.z > 0.0f) == t2) ? 1 : 0;
        ec += ((x.w > 0.0f) == t3) ? 1 : 0;

        x = xn; sv = svn; dv = dvn;
        i = j; valid = vnext;
    }

    // tail edges (E % 4, or whole range if vec path disabled)
    if (blockIdx.x == 0 && tid == 0) {
        for (int e = nvec << 2; e < E; e++) {
            int sidx = src[e], didx = dst[e];
            unsigned short ks = g_keys[sidx], kd = g_keys[didx];
            bool t = (ks == kd) && (ks != 0);
            float xe = edge_logits[e];
            es += focal_term(xe, t);
            ec += ((xe > 0.0f) == t) ? 1 : 0;
        }
    }
    block_reduce_store(es, ec, g_part_es, g_part_ec);

    // ---- final barrier; block 0 reduces partials and writes outputs ----
    if (tid == 0) { __threadfence(); atomicAdd(&g_bar1, 1u); }
    if (blockIdx.x != 0) return;
    if (tid == 0) {
        while (*(volatile unsigned int*)&g_bar1 < (unsigned int)nb) { }
    }
    __syncthreads();
    __threadfence();

    if (tid < 32) {
        double des = 0.0, dns = 0.0;
        int iec = 0, inc = 0;
        for (int k = tid; k < nb; k += 32) {
            des += (double)g_part_es[k];
            dns += (double)g_part_ns[k];
            iec += g_part_ec[k];
            inc += g_part_nc[k];
        }
        #pragma unroll
        for (int o = 16; o > 0; o >>= 1) {
            des += __shfl_down_sync(0xFFFFFFFFu, des, o);
            dns += __shfl_down_sync(0xFFFFFFFFu, dns, o);
            iec += __shfl_down_sync(0xFFFFFFFFu, iec, o);
            inc += __shfl_down_sync(0xFFFFFFFFu, inc, o);
        }
        if (tid == 0) {
            float edge_loss = (float)(des / (double)E);
            float node_loss = (float)(dns / (double)N);
            out[0] = edge_loss + node_loss;  // EDGE_W = NODE_W = 1
            out[1] = edge_loss;
            out[2] = node_loss;
            out[3] = (float)((double)iec / (double)E);
            out[4] = (float)((double)inc / (double)N);
            g_bar0 = 0;                      // reset for next graph replay
            g_bar1 = 0;
        }
    }
}

extern "C" void kernel_launch(void* const* d_in, const int* in_sizes, int n_in,
                              void* d_out, int out_size) {
    const float* edge_logits = (const float*)d_in[0];
    const float* node_logits = (const float*)d_in[1];
    const int*   batch       = (const int*)d_in[2];
    const int*   pinst       = (const int*)d_in[3];
    const int*   edge_index  = (const int*)d_in[4];

    int E = in_sizes[0];
    int N = in_sizes[1];
    const int* src = edge_index;
    const int* dst = edge_index + E;
    float* out = (float*)d_out;

    int nvec = ((E & 3) == 0) ? (E >> 2) : 0;

    int smem_bytes = ((N + 15) >> 4) << 4;   // 8-bit hash table, 16B padded
    cudaFuncSetAttribute(fused_kernel,
                         cudaFuncAttributeMaxDynamicSharedMemorySize,
                         smem_bytes);

    int sm_count = 148;
    cudaDeviceGetAttribute(&sm_count, cudaDevAttrMultiProcessorCount, 0);

    // size the grid by ACTUAL occupancy so the grid barrier cannot deadlock
    int per_sm = 1;
    cudaOccupancyMaxActiveBlocksPerMultiprocessor(&per_sm, fused_kernel,
                                                  1024, smem_bytes);
    if (per_sm < 1) per_sm = 1;
    int nblocks = sm_count * per_sm;
    if (nblocks > MAX_BLOCKS) nblocks = MAX_BLOCKS;

    fused_kernel<<<nblocks, 1024, smem_bytes>>>(edge_logits, node_logits,
                                                batch, pinst, src, dst,
                                                E, N, nvec, out);
}

// round 6
// speedup vs baseline: 1.7712x; 1.0156x over previous
#include <cuda_runtime.h>
#include <math.h>

// ---------------------------------------------------------------------------
// GNNLoss fused single-kernel (R6) = R5 + warp-uniform batched fallback +
// gather/math software scheduling.
//
// key[node]  = (pi==0) ? 0 : (batch<<10)|pi     (u16 exact; batch<16, pi<1000)
// hash[node] = (key==0) ? 0 : (key % 255) + 1   (u8 filter, 200KB, in smem)
// target     = hash mismatch -> false; both zero -> false;
//              else exact u16 key compare (~0.43% of edges).
//
// Edge loop: prefetch next chunk's 3 vec4 streams; do all 8 LDS hash gathers
// up front; resolve rare exact checks in ONE warp-uniform region with
// per-lane predicated LDGs (no per-edge divergence); then 4x focal math.
// ---------------------------------------------------------------------------

#define MAX_NODES  262144
#define MAX_BLOCKS 512

__device__ __align__(16) unsigned short g_keys[MAX_NODES];
__device__ __align__(16) unsigned char  g_hash[MAX_NODES];
__device__ float g_part_es[MAX_BLOCKS];
__device__ int   g_part_ec[MAX_BLOCKS];
__device__ float g_part_ns[MAX_BLOCKS];
__device__ int   g_part_nc[MAX_BLOCKS];
__device__ unsigned int g_bar0;   // zero-init; reset by block 0 each run
__device__ unsigned int g_bar1;

__device__ __forceinline__ float rcp_approx(float x) {
    float y;
    asm("rcp.approx.f32 %0, %1;" : "=f"(y) : "f"(x));
    return y;
}

__device__ __forceinline__ float focal_term(float x, bool t) {
    float a  = fabsf(x);
    float em = __expf(-a);             // MUFU.EX2 (+mul)
    float w  = 1.0f + em;              // w in [1,2]
    float L  = __logf(w);              // MUFU.LG2 (+mul)
    float q  = em * rcp_approx(w);     // 1 - sigmoid(|x|), MUFU.RCP ~1ulp
    bool  m  = ((x >= 0.0f) == t);
    float omp = m ? q : (1.0f - q);    // 1 - p_t
    float ce  = m ? L : (a + L);       // BCE-with-logits
    float at  = t ? 0.25f : 0.75f;     // ALPHA=0.25
    return at * ce * omp * omp;        // GAMMA=2
}

// block reduction of (float, int) -> one slot per block
__device__ __forceinline__ void block_reduce_store(float s, int c,
                                                   float* ps, int* pc) {
    #pragma unroll
    for (int o = 16; o > 0; o >>= 1) {
        s += __shfl_down_sync(0xFFFFFFFFu, s, o);
        c += __shfl_down_sync(0xFFFFFFFFu, c, o);
    }
    __shared__ float sh_s[32];
    __shared__ int   sh_c[32];
    int lane = threadIdx.x & 31;
    int wid  = threadIdx.x >> 5;
    if (lane == 0) { sh_s[wid] = s; sh_c[wid] = c; }
    __syncthreads();
    int nw = (blockDim.x + 31) >> 5;
    if (wid == 0) {
        s = (lane < nw) ? sh_s[lane] : 0.0f;
        c = (lane < nw) ? sh_c[lane] : 0;
        #pragma unroll
        for (int o = 16; o > 0; o >>= 1) {
            s += __shfl_down_sync(0xFFFFFFFFu, s, o);
            c += __shfl_down_sync(0xFFFFFFFFu, c, o);
        }
        if (lane == 0) { ps[blockIdx.x] = s; pc[blockIdx.x] = c; }
    }
    __syncthreads();
}

__device__ __forceinline__ void grid_barrier(unsigned int* bar, int nb) {
    __syncthreads();
    if (threadIdx.x == 0) {
        __threadfence();
        atomicAdd(bar, 1u);
        while (*(volatile unsigned int*)bar < (unsigned int)nb) { }
    }
    __syncthreads();
    __threadfence();
}

__global__ void __launch_bounds__(1024, 1)
fused_kernel(const float* __restrict__ edge_logits,
             const float* __restrict__ node_logits,
             const int*   __restrict__ batch,
             const int*   __restrict__ pinst,
             const int*   __restrict__ src,
             const int*   __restrict__ dst,
             int E, int N, int nvec,
             float* __restrict__ out) {
    extern __shared__ unsigned char sh[];
    int tid     = threadIdx.x;
    int nb      = gridDim.x;
    int gtid    = blockIdx.x * blockDim.x + tid;
    int gstride = nb * blockDim.x;

    // ---- phase 1: nodes (build key + hash tables, node loss/acc) ----
    float ns = 0.0f; int nc = 0;
    for (int i = gtid; i < N; i += gstride) {
        int p = pinst[i];
        int b = batch[i];
        unsigned short key = (p == 0) ? (unsigned short)0
                                      : (unsigned short)((b << 10) | p);
        g_keys[i] = key;
        g_hash[i] = (key == 0) ? (unsigned char)0
                               : (unsigned char)((key % 255) + 1);
        float x = node_logits[i];
        bool  t = (p != 0);
        ns += focal_term(x, t);
        nc += ((x > 0.0f) == t) ? 1 : 0;
    }
    block_reduce_store(ns, nc, g_part_ns, g_part_nc);

    grid_barrier(&g_bar0, nb);   // tables complete, visible in L2

    // ---- broadcast hash table into shared memory ----
    int nw4 = (N + 15) >> 4;
    const uint4* hv = (const uint4*)g_hash;
    uint4* s4 = (uint4*)sh;
    for (int i = tid; i < nw4; i += blockDim.x) s4[i] = hv[i];
    __syncthreads();

    // ---- phase 2: edges, pipelined + batched fallback ----
    const float4* elv = (const float4*)edge_logits;
    const int4*   svp = (const int4*)src;
    const int4*   dvp = (const int4*)dst;
    float es = 0.0f; int ec = 0;

    int i = gtid;
    float4 x;  int4 sv, dv;
    bool valid = (i < nvec);
    if (valid) {
        x  = __ldcs(&elv[i]);
        sv = __ldcs(&svp[i]);
        dv = __ldcs(&dvp[i]);
    }
    while (valid) {
        int j = i + gstride;
        bool vnext = (j < nvec);
        float4 xn; int4 svn, dvn;
        if (vnext) {                      // prefetch next chunk first
            xn  = __ldcs(&elv[j]);
            svn = __ldcs(&svp[j]);
            dvn = __ldcs(&dvp[j]);
        }

        // all 8 hash gathers up front (LDS latency overlaps math below)
        unsigned int h0s = sh[sv.x], h0d = sh[dv.x];
        unsigned int h1s = sh[sv.y], h1d = sh[dv.y];
        unsigned int h2s = sh[sv.z], h2d = sh[dv.z];
        unsigned int h3s = sh[sv.w], h3d = sh[dv.w];

        bool n0 = (h0s == h0d) & (h0s != 0u);
        bool n1 = (h1s == h1d) & (h1s != 0u);
        bool n2 = (h2s == h2d) & (h2s != 0u);
        bool n3 = (h3s == h3d) & (h3s != 0u);

        // rare exact checks: ONE warp-uniform region, per-lane predication
        unsigned short ks0 = 0, kd0 = 0, ks1 = 0, kd1 = 0;
        unsigned short ks2 = 0, kd2 = 0, ks3 = 0, kd3 = 0;
        unsigned int amask = __activemask();
        if (__any_sync(amask, n0 | n1 | n2 | n3)) {
            ks0 = n0 ? __ldg(&g_keys[sv.x]) : ks0;
            kd0 = n0 ? __ldg(&g_keys[dv.x]) : kd0;
            ks1 = n1 ? __ldg(&g_keys[sv.y]) : ks1;
            kd1 = n1 ? __ldg(&g_keys[dv.y]) : kd1;
            ks2 = n2 ? __ldg(&g_keys[sv.z]) : ks2;
            kd2 = n2 ? __ldg(&g_keys[dv.z]) : kd2;
            ks3 = n3 ? __ldg(&g_keys[sv.w]) : ks3;
            kd3 = n3 ? __ldg(&g_keys[dv.w]) : kd3;
        }
        bool t0 = n0 & (ks0 == kd0);
        bool t1 = n1 & (ks1 == kd1);
        bool t2 = n2 & (ks2 == kd2);
        bool t3 = n3 & (ks3 == kd3);

        es += focal_term(x.x, t0);
        es += focal_term(x.y, t1);
        es += focal_term(x.z, t2);
        es += focal_term(x.w, t3);

        ec += ((x.x > 0.0f) == t0) ? 1 : 0;
        ec += ((x.y > 0.0f) == t1) ? 1 : 0;
        ec += ((x.z > 0.0f) == t2) ? 1 : 0;
        ec += ((x.w > 0.0f) == t3) ? 1 : 0;

        x = xn; sv = svn; dv = dvn;
        i = j; valid = vnext;
    }

    // tail edges (E % 4, or whole range if vec path disabled)
    if (blockIdx.x == 0 && tid == 0) {
        for (int e = nvec << 2; e < E; e++) {
            int sidx = src[e], didx = dst[e];
            unsigned short ks = g_keys[sidx], kd = g_keys[didx];
            bool t = (ks == kd) && (ks != 0);
            float xe = edge_logits[e];
            es += focal_term(xe, t);
            ec += ((xe > 0.0f) == t) ? 1 : 0;
        }
    }
    block_reduce_store(es, ec, g_part_es, g_part_ec);

    // ---- final barrier; block 0 reduces partials and writes outputs ----
    if (tid == 0) { __threadfence(); atomicAdd(&g_bar1, 1u); }
    if (blockIdx.x != 0) return;
    if (tid == 0) {
        while (*(volatile unsigned int*)&g_bar1 < (unsigned int)nb) { }
    }
    __syncthreads();
    __threadfence();

    if (tid < 32) {
        double des = 0.0, dns = 0.0;
        int iec = 0, inc = 0;
        for (int k = tid; k < nb; k += 32) {
            des += (double)g_part_es[k];
            dns += (double)g_part_ns[k];
            iec += g_part_ec[k];
            inc += g_part_nc[k];
        }
        #pragma unroll
        for (int o = 16; o > 0; o >>= 1) {
            des += __shfl_down_sync(0xFFFFFFFFu, des, o);
            dns += __shfl_down_sync(0xFFFFFFFFu, dns, o);
            iec += __shfl_down_sync(0xFFFFFFFFu, iec, o);
            inc += __shfl_down_sync(0xFFFFFFFFu, inc, o);
        }
        if (tid == 0) {
            float edge_loss = (float)(des / (double)E);
            float node_loss = (float)(dns / (double)N);
            out[0] = edge_loss + node_loss;  // EDGE_W = NODE_W = 1
            out[1] = edge_loss;
            out[2] = node_loss;
            out[3] = (float)((double)iec / (double)E);
            out[4] = (float)((double)inc / (double)N);
            g_bar0 = 0;                      // reset for next graph replay
            g_bar1 = 0;
        }
    }
}

extern "C" void kernel_launch(void* const* d_in, const int* in_sizes, int n_in,
                              void* d_out, int out_size) {
    const float* edge_logits = (const float*)d_in[0];
    const float* node_logits = (const float*)d_in[1];
    const int*   batch       = (const int*)d_in[2];
    const int*   pinst       = (const int*)d_in[3];
    const int*   edge_index  = (const int*)d_in[4];

    int E = in_sizes[0];
    int N = in_sizes[1];
    const int* src = edge_index;
    const int* dst = edge_index + E;
    float* out = (float*)d_out;

    int nvec = ((E & 3) == 0) ? (E >> 2) : 0;

    int smem_bytes = ((N + 15) >> 4) << 4;   // 8-bit hash table, 16B padded
    cudaFuncSetAttribute(fused_kernel,
                         cudaFuncAttributeMaxDynamicSharedMemorySize,
                         smem_bytes);

    int sm_count = 148;
    cudaDeviceGetAttribute(&sm_count, cudaDevAttrMultiProcessorCount, 0);

    // size the grid by ACTUAL occupancy so the grid barrier cannot deadlock
    int per_sm = 1;
    cudaOccupancyMaxActiveBlocksPerMultiprocessor(&per_sm, fused_kernel,
                                                  1024, smem_bytes);
    if (per_sm < 1) per_sm = 1;
    int nblocks = sm_count * per_sm;
    if (nblocks > MAX_BLOCKS) nblocks = MAX_BLOCKS;

    fused_kernel<<<nblocks, 1024, smem_bytes>>>(edge_logits, node_logits,
                                                batch, pinst, src, dst,
                                                E, N, nvec, out);
}